// round 11
// baseline (speedup 1.0000x reference)
#include <cuda_runtime.h>
#include <math.h>
#include <stdint.h>

#define Bn 64
#define Dn 256
#define Hn 512
#define Rn 32
#define CLIPV 50.0f
#define TB1 8    // batches per P1 main block

// Output layout (concatenation of the returned tuple, fp32):
//   v_new      [64,512]      @ 0
//   new_h      [64,512]      @ 32768
//   dU_new     [64,512,512]  @ 65536
//   new_trace_e[64,512]      @ 16842752
//   new_trace_E[64,512,512]  @ 16875520
#define OFF_V    ((size_t)0)
#define OFF_NH   ((size_t)32768)
#define OFF_DU   ((size_t)65536)
#define OFF_TEO  ((size_t)16842752)
#define OFF_TEE  ((size_t)16875520)

// Device-global scratch (allocation-free)
__device__ float g_up[Hn * Hn];
__device__ float g_lo[Hn * Hn];
__device__ float g_suMod[Bn];
__device__ float g_sE;
__device__ float g_omU;

__device__ __forceinline__ float sigmoidf_(float x) {
    return 1.0f / (1.0f + expf(-x));
}

__device__ __forceinline__ void cp_async16(uint32_t saddr, const float* gaddr) {
    asm volatile("cp.async.cg.shared.global [%0], [%1], 16;\n"
                 :: "r"(saddr), "l"(gaddr) : "memory");
}
__device__ __forceinline__ void cp_commit() {
    asm volatile("cp.async.commit_group;\n" ::: "memory");
}
__device__ __forceinline__ void cp_wait1() {
    asm volatile("cp.async.wait_group 1;\n" ::: "memory");
}

// ---------------------------------------------------------------------------
// P1: 1088 blocks x 128 threads, 16KB dynamic smem, __launch_bounds__(128,8)
// -> 8 blocks/SM co-resident = ~29 warps/SM (vs 15 before). ONE wave
// (capacity 8*152=1216 >= 1088).
// Smem = per-warp cp.async double-buffered dU tiles ONLY (4 warps x 2 x 2KB).
// NO block-level staging, NO __syncthreads in the main path: h, x, alpha,
// h2h_w, x2h_w are read via __ldg (L1/L2-hot: alpha/W rows reused 8x per
// block and 8x across b-group blocks; h/x tiny).
//  bx < 1024 : main slice. gx = bx & 127 -> i-group, gy = bx >> 7 -> b0.
//              Warp-per-i, TB1=8 rows, cp.async double buffering.
//              gy==0 blocks also fold in the clip-bound precompute.
//  bx >= 1024: mod slice for b = bx - 1024 (free, inside the main wave).
// ---------------------------------------------------------------------------
__global__ __launch_bounds__(128, 8) void p1_kernel(
    const float* __restrict__ x, const float* __restrict__ h,
    const float* __restrict__ v, const float* __restrict__ dU,
    const float* __restrict__ trace_e, const float* __restrict__ x2h_w,
    const float* __restrict__ x2h_b, const float* __restrict__ h2h_w,
    const float* __restrict__ h2h_b, const float* __restrict__ alpha,
    const float* __restrict__ tau_v, const float* __restrict__ tau_e,
    const float* __restrict__ tau_U, const float* __restrict__ tau_E,
    float* __restrict__ out) {
    extern __shared__ float smem[];
    const int warp = threadIdx.x >> 5;
    const int lane = threadIdx.x & 31;

    if (blockIdx.x >= 1024) {
        // ---- mod slice ----
        const int b = blockIdx.x - 1024;
        float* sm = smem;  // 4 floats of scratch

        const float4* xb = (const float4*)(x + (size_t)b * Dn);
        const float4* hb = (const float4*)(h + (size_t)b * Hn);

        float acc = 0.f;
#pragma unroll
        for (int t = 0; t < 8; t++) {
            const int r = warp + 4 * t;
            const int o = Hn + r;
            const float4* xw = (const float4*)(x2h_w + (size_t)o * Dn);
            const float4* hw = (const float4*)(h2h_w + (size_t)o * Hn);
            float s = 0.f;
#pragma unroll
            for (int c = 0; c < 2; c++) {
                const float4 W4 = xw[c * 32 + lane];
                const float4 V4 = xb[c * 32 + lane];
                s = fmaf(W4.x, V4.x, s); s = fmaf(W4.y, V4.y, s);
                s = fmaf(W4.z, V4.z, s); s = fmaf(W4.w, V4.w, s);
            }
#pragma unroll
            for (int c = 0; c < 4; c++) {
                const float4 W4 = hw[c * 32 + lane];
                const float4 V4 = hb[c * 32 + lane];
                s = fmaf(W4.x, V4.x, s); s = fmaf(W4.y, V4.y, s);
                s = fmaf(W4.z, V4.z, s); s = fmaf(W4.w, V4.w, s);
            }
#pragma unroll
            for (int off = 16; off; off >>= 1)
                s += __shfl_xor_sync(0xffffffffu, s, off);
            if (lane == 0) acc += fmaxf(s + x2h_b[o] + h2h_b[o], 0.f);
        }
        if (lane == 0) sm[warp] = acc;
        __syncthreads();
        if (threadIdx.x == 0) {
            const float m  = sm[0] + sm[1] + sm[2] + sm[3];
            const float sU = sigmoidf_(tau_U[0]);
            g_suMod[b] = sU * m;
            if (b == 0) {
                g_sE  = sigmoidf_(tau_E[0]);
                g_omU = 1.0f - sU;
            }
        }
        return;
    }

    // ---- main reduction slice ----
    const int gx = blockIdx.x & 127;
    const int gy = blockIdx.x >> 7;
    const int i  = gx * 4 + warp;
    const int b0 = gy * TB1;
    const int jb = lane * 4;

    const float* arow = alpha + (size_t)i * Hn;
    const float* wrow = h2h_w + (size_t)i * Hn;

    // Clip-bound fold: one block column computes up/lo (temp regs only).
    if (gy == 0) {
#pragma unroll
        for (int c = 0; c < 4; c++) {
            const int j = c * 128 + jb;
            const float4 A = __ldg((const float4*)(arow + j));
            const float4 W = __ldg((const float4*)(wrow + j));
            float4 up, lo;
            {
                const float d = fmaxf(A.x, 0.f) + 1e-8f;
                up.x = fmaxf(CLIPV - W.x, 0.f) / d;
                lo.x = -fmaxf(CLIPV + W.x, 0.f) / d;
            }
            {
                const float d = fmaxf(A.y, 0.f) + 1e-8f;
                up.y = fmaxf(CLIPV - W.y, 0.f) / d;
                lo.y = -fmaxf(CLIPV + W.y, 0.f) / d;
            }
            {
                const float d = fmaxf(A.z, 0.f) + 1e-8f;
                up.z = fmaxf(CLIPV - W.z, 0.f) / d;
                lo.z = -fmaxf(CLIPV + W.z, 0.f) / d;
            }
            {
                const float d = fmaxf(A.w, 0.f) + 1e-8f;
                up.w = fmaxf(CLIPV - W.w, 0.f) / d;
                lo.w = -fmaxf(CLIPV + W.w, 0.f) / d;
            }
            *(float4*)(g_up + (size_t)i * Hn + j) = up;
            *(float4*)(g_lo + (size_t)i * Hn + j) = lo;
        }
    }

    const float bias = x2h_b[i] + h2h_b[i];
    const float sv   = sigmoidf_(tau_v[i]);
    const float se   = sigmoidf_(tau_e[i]);

    // Per-warp double-buffered dU tiles (write bytes, read floats: matched).
    const uint32_t du_smem = (uint32_t)__cvta_generic_to_shared(smem);
    const uint32_t tile0w = du_smem + ((warp * 2 + 0) * 512 + jb) * 4;
    const uint32_t tile1w = du_smem + ((warp * 2 + 1) * 512 + jb) * 4;
    const float* tile0g = smem + (warp * 2 + 0) * 512 + jb;
    const float* tile1g = smem + (warp * 2 + 1) * 512 + jb;

    const float* dUrow = dU + ((size_t)b0 * Hn + i) * Hn;  // row base for b0
    const size_t bstride = (size_t)Hn * Hn;                // next b, same i

    // prime the pipeline: rows 0 and 1
#pragma unroll
    for (int c = 0; c < 4; c++)
        cp_async16(tile0w + c * 512, dUrow + c * 128 + jb);
    cp_commit();
#pragma unroll
    for (int c = 0; c < 4; c++)
        cp_async16(tile1w + c * 512, dUrow + bstride + c * 128 + jb);
    cp_commit();

    for (int bb = 0; bb < TB1; bb++) {
        const int b = b0 + bb;
        cp_wait1();   // tile for row bb is ready

        const float* buf = (bb & 1) ? tile1g : tile0g;

        float p0 = 0.f, p1 = 0.f, p2 = 0.f, p3 = 0.f;
#pragma unroll
        for (int c = 0; c < 4; c++) {
            const int j = c * 128 + jb;
            const float4 D4 = *(const float4*)(buf + c * 128);
            const float4 A4 = __ldg((const float4*)(arow + j));
            const float4 W4 = __ldg((const float4*)(wrow + j));
            const float4 H4 = __ldg((const float4*)(h + (size_t)b * Hn + j));
            p0 = fmaf(fmaf(fmaxf(A4.x, 0.f), D4.x, W4.x), H4.x, p0);
            p1 = fmaf(fmaf(fmaxf(A4.y, 0.f), D4.y, W4.y), H4.y, p1);
            p2 = fmaf(fmaf(fmaxf(A4.z, 0.f), D4.z, W4.z), H4.z, p2);
            p3 = fmaf(fmaf(fmaxf(A4.w, 0.f), D4.w, W4.w), H4.w, p3);
        }
#pragma unroll
        for (int c = 0; c < 2; c++) {
            const int j = c * 128 + jb;
            const float4 XW = __ldg((const float4*)(x2h_w + (size_t)i * Dn + j));
            const float4 X4 = __ldg((const float4*)(x + (size_t)b * Dn + j));
            p0 = fmaf(XW.x, X4.x, p0);
            p1 = fmaf(XW.y, X4.y, p1);
            p2 = fmaf(XW.z, X4.z, p2);
            p3 = fmaf(XW.w, X4.w, p3);
        }

        float p = (p0 + p1) + (p2 + p3);
#pragma unroll
        for (int off = 16; off; off >>= 1)
            p += __shfl_xor_sync(0xffffffffu, p, off);
        // butterfly done -> LDS reads of `buf` completed; refill is safe.

        if (bb + 2 < TB1) {
            const uint32_t tw = (bb & 1) ? tile1w : tile0w;
            const float* g = dUrow + (size_t)(bb + 2) * bstride;
#pragma unroll
            for (int c = 0; c < 4; c++)
                cp_async16(tw + c * 512, g + c * 128 + jb);
        }
        cp_commit();  // uniform group accounting

        if (lane == 0) {
            const float vb  = __ldg(v + (size_t)b * Hn + i);
            const float teS = __ldg(trace_e + (size_t)b * Hn + i);
            const float hbi = __ldg(h + (size_t)b * Hn + i);
            const float dv  = p + bias;
            const float vn  = fmaf(sv, dv - vb, vb);
            const float nte = fmaf(se, hbi - teS, teS);
            out[OFF_V   + (size_t)b * Hn + i] = vn;
            out[OFF_NH  + (size_t)b * Hn + i] = fmaxf(vn, 0.f);
            out[OFF_TEO + (size_t)b * Hn + i] = nte;
        }
    }
}

// ---------------------------------------------------------------------------
// P2: pure streaming elementwise pass over the HxH matrices.
// 4 independent tasks per thread; trace_E via __ldcs; outputs via __stcs.
// ---------------------------------------------------------------------------
#define P2_BLOCKS 4096
#define P2_THREADS 256
#define P2_TOTAL  ((size_t)Bn * Hn * 128)
#define P2_QTR    (P2_TOTAL / 4)

__global__ __launch_bounds__(P2_THREADS) void p2_kernel(
    const float* __restrict__ dU, const float* __restrict__ trace_E,
    const float* __restrict__ h, const float* __restrict__ trace_e,
    float* __restrict__ out) {
    const size_t gid = (size_t)blockIdx.x * P2_THREADS + threadIdx.x;
    const float sE  = g_sE;
    const float omU = g_omU;

    const float4* dU4 = (const float4*)dU;
    const float4* tE4 = (const float4*)trace_E;
    const float4* h4p = (const float4*)h;
    const float4* te4p = (const float4*)trace_e;
    const float4* up4 = (const float4*)g_up;
    const float4* lo4 = (const float4*)g_lo;
    float4* outDU = (float4*)(out + OFF_DU);
    float4* outTE = (float4*)(out + OFF_TEE);

#pragma unroll
    for (int q = 0; q < 4; q++) {
        const size_t t = gid + (size_t)q * P2_QTR;
        const int j4  = (int)(t & 127);
        const size_t row = t >> 7;           // b*512 + i
        const int i = (int)(row & 511);
        const int b = (int)(row >> 9);

        const float4 du = dU4[t];
        const float4 tE = __ldcs(&tE4[t]);
        const float4 hh = h4p[((size_t)b << 7) + j4];
        const float4 te = te4p[((size_t)b << 7) + j4];
        const float4 up = up4[((size_t)i << 7) + j4];
        const float4 lo = lo4[((size_t)i << 7) + j4];
        const float nh  = __ldg(out + OFF_NH  + row);
        const float nte = __ldg(out + OFF_TEO + row);
        const float suMod = g_suMod[b];

        float4 tOut, dOut;
        {
            const float o = nh * te.x - nte * hh.x;
            tOut.x = fmaf(sE, o - tE.x, tE.x);
            dOut.x = fmaxf(fminf(fmaf(suMod, tOut.x, omU * du.x), up.x), lo.x);
        }
        {
            const float o = nh * te.y - nte * hh.y;
            tOut.y = fmaf(sE, o - tE.y, tE.y);
            dOut.y = fmaxf(fminf(fmaf(suMod, tOut.y, omU * du.y), up.y), lo.y);
        }
        {
            const float o = nh * te.z - nte * hh.z;
            tOut.z = fmaf(sE, o - tE.z, tE.z);
            dOut.z = fmaxf(fminf(fmaf(suMod, tOut.z, omU * du.z), up.z), lo.z);
        }
        {
            const float o = nh * te.w - nte * hh.w;
            tOut.w = fmaf(sE, o - tE.w, tE.w);
            dOut.w = fmaxf(fminf(fmaf(suMod, tOut.w, omU * du.w), up.w), lo.w);
        }
        __stcs(&outTE[t], tOut);
        __stcs(&outDU[t], dOut);
    }
}

extern "C" void kernel_launch(void* const* d_in, const int* in_sizes, int n_in,
                              void* d_out, int out_size) {
    const float* x       = (const float*)d_in[0];
    const float* h       = (const float*)d_in[1];
    const float* v       = (const float*)d_in[2];
    const float* dU      = (const float*)d_in[3];
    const float* trace_e = (const float*)d_in[4];
    const float* trace_E = (const float*)d_in[5];
    const float* x2h_w   = (const float*)d_in[6];
    const float* x2h_b   = (const float*)d_in[7];
    const float* h2h_w   = (const float*)d_in[8];
    const float* h2h_b   = (const float*)d_in[9];
    const float* alpha   = (const float*)d_in[10];
    const float* tau_v   = (const float*)d_in[11];
    const float* tau_e   = (const float*)d_in[12];
    const float* tau_U   = (const float*)d_in[13];
    const float* tau_E   = (const float*)d_in[14];
    float* out = (float*)d_out;

    const int p1_smem = 4096 * 4;  // 16KB per-warp dU double buffers
    p1_kernel<<<1088, 128, p1_smem>>>(x, h, v, dU, trace_e, x2h_w, x2h_b,
                                      h2h_w, h2h_b, alpha, tau_v, tau_e,
                                      tau_U, tau_E, out);
    p2_kernel<<<P2_BLOCKS, P2_THREADS>>>(dU, trace_E, h, trace_e, out);
}